// round 14
// baseline (speedup 1.0000x reference)
#include <cuda_runtime.h>
#include <cuda_bf16.h>
#include <math.h>
#include <stdint.h>

// Problem constants: M=8 modules, B=64 batch, S=128 seq, D=512, H=8 heads (hd=64), FF=1024.

// Scratch (static device array; no runtime allocation).
__device__ float g_scratch[11012096];

__device__ __forceinline__ uint32_t smem_u32(const void* p){
    uint32_t a;
    asm("{ .reg .u64 t; cvta.to.shared.u64 t, %1; cvt.u32.u64 %0, t; }" : "=r"(a) : "l"(p));
    return a;
}
__device__ __forceinline__ void cpasync16(uint32_t dst, const float* src){
    asm volatile("cp.async.cg.shared.global [%0], [%1], 16;" :: "r"(dst), "l"(src) : "memory");
}
__device__ __forceinline__ uint32_t cvt_tf32(float x){
    uint32_t r; asm("cvt.rna.tf32.f32 %0, %1;" : "=r"(r) : "f"(x)); return r;
}
__device__ __forceinline__ void cp_commit(){
    asm volatile("cp.async.commit_group;" ::: "memory");
}
// wait until at most n groups pending
__device__ __forceinline__ void cp_wait(int n){
    if (n <= 0)      asm volatile("cp.async.wait_group 0;" ::: "memory");
    else if (n == 1) asm volatile("cp.async.wait_group 1;" ::: "memory");
    else if (n == 2) asm volatile("cp.async.wait_group 2;" ::: "memory");
    else             asm volatile("cp.async.wait_group 3;" ::: "memory");
}
// PDL: block until predecessor kernel's writes are visible.
__device__ __forceinline__ void pdl_wait(){
    asm volatile("griddepcontrol.wait;" ::: "memory");
}
#define MMA_TF32(acc, af, bf) \
    asm volatile( \
        "mma.sync.aligned.m16n8k8.row.col.f32.tf32.tf32.f32 " \
        "{%0,%1,%2,%3}, {%4,%5,%6,%7}, {%8,%9}, {%0,%1,%2,%3};" \
        : "+f"((acc)[0]), "+f"((acc)[1]), "+f"((acc)[2]), "+f"((acc)[3]) \
        : "r"((af)[0]), "r"((af)[1]), "r"((af)[2]), "r"((af)[3]), \
          "r"((bf)[0]), "r"((bf)[1]))

struct EpiArgs {
    const float* wg2;    // gate: Wg2 base [4*M][FF]
    float*       gatez;  // gate: partial sums [8][32][64]
    const float* gzin;   // EPI2: gate partials (read)
    const float* bg2;    // EPI2: [4*M]
    const float* p0; const float* p1; const float* p2; const float* p3;  // prev q,k,v,state
    const float* wAlt;   // EPI3: Wg1
    const float* bAlt;   // EPI3: bg1
};

// ===========================================================================
// cp.async NSTG-stage tf32 mma GEMM (NN: W rows n-contiguous), PDL-aware.
//   C[64 x N] = act( A[64 x K] @ W[K x N] + bias )  per batch (b1,b0)
// A swizzled in SMEM: (r,k) at word r*32 + ((k>>2 ^ (r&7))<<2) + (k&3).
// Prefetch distance = NSTG-1 chunks; steady-state wait_group NSTG-2.
// EPI: 0 = store C
//      2 = final combine (tanh/gate/prev-mix, writes d_out)
//      3 = dual MLP: blockIdx.x<8 -> store C (h); >=8 -> gate partial
//      4 = store C + x[:,512+n] = relu(prev_state)  (concat fold-in)
// ===========================================================================
template<int ACT, int BN, int EPI, int NSTG>
__global__ __launch_bounds__(256) void mma_async_kernel(
    const float* __restrict__ A, int lda, int sA1, int sA0,
    const float* __restrict__ W, int ldw, int sW1, int sW0,
    float* __restrict__ C, int ldc, int sC1, int sC0,
    const float* __restrict__ bias, int sB1, int sB0,
    int K, int inner, EpiArgs epi)
{
    extern __shared__ float smemf[];
    constexpr int A_F = 64 * 32;
    constexpr int BSTR = BN + 4;
    constexpr int B_F = 32 * BSTR;
    constexpr int STAGE_F = A_F + B_F;
    constexpr int BITER = BN / 32;
    constexpr int NA = BN / 32;
    constexpr int PFD = NSTG - 1;     // prefetch distance
    constexpr int CAP = NSTG - 2;     // steady-state trailing groups

    const int tid = threadIdx.x;
    const int wid = tid >> 5, lane = tid & 31;
    const int g = lane >> 2, tig = lane & 3;
    const int warp_m = wid >> 2;
    const int warp_n = wid & 3;
    const int batch = blockIdx.y;
    const int b1 = batch / inner;
    const int b0 = batch - b1 * inner;
    const int nx = (EPI == 3) ? (blockIdx.x & 7) : blockIdx.x;
    const int n0 = nx * BN;
    const bool gp = (EPI == 3) && (blockIdx.x >= 8);

    const float* Wsel = gp ? epi.wAlt : W;
    const float* Bsel = gp ? epi.bAlt : bias;

    const float* Ab = A + (size_t)b1 * sA1 + (size_t)b0 * sA0;
    const float* Wb = Wsel + (size_t)b1 * sW1 + (size_t)b0 * sW0 + n0;
    const float* Bb = Bsel ? Bsel + (size_t)b1 * sB1 + (size_t)b0 * sB0 + n0 : nullptr;
    float* Cb;
    if (EPI == 2)
        Cb = C + (size_t)(((b1 + 1) & 3)) * 262144 + (size_t)b0 * 32768 + n0;
    else
        Cb = C + (size_t)b1 * sC1 + (size_t)b0 * sC0 + n0;

    const uint32_t sbase = smem_u32(smemf);
    const int NC = K >> 5;

    auto issueA = [&](int c){
        const int k0 = c << 5;
        const uint32_t sb = sbase + (uint32_t)(c % NSTG) * (STAGE_F * 4);
        #pragma unroll
        for (int i = 0; i < 2; i++){
            int f = tid + (i << 8);
            int r = f >> 3, kq = f & 7;
            cpasync16(sb + (uint32_t)(r * 32 + ((kq ^ (r & 7)) << 2)) * 4,
                      Ab + (size_t)r * lda + k0 + (kq << 2));
        }
    };
    auto issueB = [&](int c){
        const int k0 = c << 5;
        const uint32_t sb = sbase + (uint32_t)(c % NSTG) * (STAGE_F * 4);
        #pragma unroll
        for (int i = 0; i < BITER; i++){
            int f = tid + (i << 8);
            int k = f / (BN >> 2), nq = f % (BN >> 2);
            cpasync16(sb + (uint32_t)(A_F + k * BSTR + (nq << 2)) * 4,
                      Wb + (size_t)(k0 + k) * ldw + (nq << 2));
        }
    };

    float acc[2][NA][4];
    #pragma unroll
    for (int i = 0; i < 2; i++)
        #pragma unroll
        for (int j = 0; j < NA; j++)
            #pragma unroll
            for (int u = 0; u < 4; u++) acc[i][j][u] = 0.f;

    // PDL prologue: stream independent weights first, wait, then A.
    const int PRE = (NC < PFD) ? NC : PFD;
    for (int s = 0; s < PRE; s++) issueB(s);
    pdl_wait();
    for (int s = 0; s < PRE; s++){ issueA(s); cp_commit(); }

    for (int c = 0; c < NC; ++c){
        const int rem = NC - 1 - c;
        cp_wait(rem < CAP ? rem : CAP);
        __syncthreads();
        if (c + PFD < NC){
            issueA(c + PFD);
            issueB(c + PFD);
            cp_commit();
        }

        const uint32_t* Au = reinterpret_cast<const uint32_t*>(smemf + (c % NSTG) * STAGE_F);
        const uint32_t* Bu = Au + A_F;
        #pragma unroll
        for (int ks = 0; ks < 4; ks++){
            const int kk = ks << 3;
            const int cb = kk >> 2;
            uint32_t af[2][4];
            #pragma unroll
            for (int ma = 0; ma < 2; ma++){
                const int r0 = warp_m * 32 + ma * 16 + g;
                const int r1 = r0 + 8;
                af[ma][0] = Au[r0 * 32 + ((cb ^ g) << 2) + tig];
                af[ma][1] = Au[r1 * 32 + ((cb ^ g) << 2) + tig];
                af[ma][2] = Au[r0 * 32 + (((cb + 1) ^ g) << 2) + tig];
                af[ma][3] = Au[r1 * 32 + (((cb + 1) ^ g) << 2) + tig];
            }
            uint32_t bf[NA][2];
            #pragma unroll
            for (int na = 0; na < NA; na++){
                const int cl = warp_n * (BN / 4) + na * 8 + g;
                bf[na][0] = Bu[(kk + tig) * BSTR + cl];
                bf[na][1] = Bu[(kk + tig + 4) * BSTR + cl];
            }
            #pragma unroll
            for (int ma = 0; ma < 2; ma++)
                #pragma unroll
                for (int na = 0; na < NA; na++)
                    MMA_TF32(acc[ma][na], af[ma], bf[na]);
        }
        __syncthreads();
    }

    if (EPI == 0 || EPI == 4 || (EPI == 3 && !gp)){
        #pragma unroll
        for (int ma = 0; ma < 2; ma++){
            const int r0 = warp_m * 32 + ma * 16 + g;
            #pragma unroll
            for (int na = 0; na < NA; na++){
                const int cl = warp_n * (BN / 4) + na * 8 + 2 * tig;
                float b0v = Bb ? Bb[cl] : 0.f;
                float b1v = Bb ? Bb[cl + 1] : 0.f;
                float v0 = acc[ma][na][0] + b0v, v1 = acc[ma][na][1] + b1v;
                float v2 = acc[ma][na][2] + b0v, v3 = acc[ma][na][3] + b1v;
                if (ACT >= 1){
                    v0 = fmaxf(v0, 0.f); v1 = fmaxf(v1, 0.f);
                    v2 = fmaxf(v2, 0.f); v3 = fmaxf(v3, 0.f);
                }
                if (ACT == 2){
                    v0 = tanhf(v0); v1 = tanhf(v1); v2 = tanhf(v2); v3 = tanhf(v3);
                }
                *reinterpret_cast<float2*>(Cb + (size_t)r0 * ldc + cl) = make_float2(v0, v1);
                *reinterpret_cast<float2*>(Cb + (size_t)(r0 + 8) * ldc + cl) = make_float2(v2, v3);
            }
        }
        if (EPI == 4){
            // fold-in: x[m][b][512 + n0 + cl] = relu(prev_state[m][b][n0 + cl])
            const float* ps = epi.p3 + (size_t)b1 * 32768 + n0;
            #pragma unroll
            for (int ma = 0; ma < 2; ma++){
                const int r0 = warp_m * 32 + ma * 16 + g;
                #pragma unroll
                for (int na = 0; na < NA; na++){
                    const int cl = warp_n * (BN / 4) + na * 8 + 2 * tig;
                    float2 pv0 = *reinterpret_cast<const float2*>(ps + (size_t)r0 * 512 + cl);
                    float2 pv1 = *reinterpret_cast<const float2*>(ps + (size_t)(r0 + 8) * 512 + cl);
                    *reinterpret_cast<float2*>(Cb + 512 + (size_t)r0 * ldc + cl) =
                        make_float2(fmaxf(pv0.x, 0.f), fmaxf(pv0.y, 0.f));
                    *reinterpret_cast<float2*>(Cb + 512 + (size_t)(r0 + 8) * ldc + cl) =
                        make_float2(fmaxf(pv1.x, 0.f), fmaxf(pv1.y, 0.f));
                }
            }
        }
    } else if (EPI == 3){   // gate partial path
        const float* wg2 = epi.wg2 + (size_t)batch * 1024 + n0;
        float* gbuf = smemf + NSTG * STAGE_F;   // [4 warp_n][64 rows]
        float s[2][2];
        #pragma unroll
        for (int ma = 0; ma < 2; ma++){ s[ma][0] = 0.f; s[ma][1] = 0.f; }
        #pragma unroll
        for (int na = 0; na < NA; na++){
            const int cl = warp_n * (BN / 4) + na * 8 + 2 * tig;
            const float b0v = Bb[cl], b1v = Bb[cl + 1];
            const float w0 = wg2[cl], w1 = wg2[cl + 1];
            #pragma unroll
            for (int ma = 0; ma < 2; ma++){
                s[ma][0] += fmaxf(acc[ma][na][0] + b0v, 0.f) * w0
                          + fmaxf(acc[ma][na][1] + b1v, 0.f) * w1;
                s[ma][1] += fmaxf(acc[ma][na][2] + b0v, 0.f) * w0
                          + fmaxf(acc[ma][na][3] + b1v, 0.f) * w1;
            }
        }
        #pragma unroll
        for (int ma = 0; ma < 2; ma++)
            #pragma unroll
            for (int hh = 0; hh < 2; hh++){
                s[ma][hh] += __shfl_xor_sync(0xffffffffu, s[ma][hh], 1);
                s[ma][hh] += __shfl_xor_sync(0xffffffffu, s[ma][hh], 2);
            }
        if (tig == 0){
            #pragma unroll
            for (int ma = 0; ma < 2; ma++){
                gbuf[warp_n * 64 + warp_m * 32 + ma * 16 + g]     = s[ma][0];
                gbuf[warp_n * 64 + warp_m * 32 + ma * 16 + g + 8] = s[ma][1];
            }
        }
        __syncthreads();
        if (tid < 64){
            float p = gbuf[tid] + gbuf[64 + tid] + gbuf[128 + tid] + gbuf[192 + tid];
            epi.gatez[((size_t)nx * 32 + batch) * 64 + tid] = p;
        }
    } else if (EPI == 2){   // final combine
        const float bg2v = epi.bg2[batch];
        const float* prev;
        if      (b1 == 0) prev = epi.p0;
        else if (b1 == 1) prev = epi.p1;
        else if (b1 == 2) prev = epi.p2;
        else              prev = epi.p3;
        prev += (size_t)b0 * 32768 + n0;
        #pragma unroll
        for (int ma = 0; ma < 2; ma++){
            const int r0 = warp_m * 32 + ma * 16 + g;
            const int r1 = r0 + 8;
            float gz0 = 0.f, gz1 = 0.f;
            #pragma unroll
            for (int i = 0; i < 8; i++){
                gz0 += epi.gzin[((size_t)i * 32 + batch) * 64 + r0];
                gz1 += epi.gzin[((size_t)i * 32 + batch) * 64 + r1];
            }
            const float gv0 = 1.f / (1.f + __expf(-(gz0 + bg2v)));
            const float gv1 = 1.f / (1.f + __expf(-(gz1 + bg2v)));
            #pragma unroll
            for (int na = 0; na < NA; na++){
                const int cl = warp_n * (BN / 4) + na * 8 + 2 * tig;
                const float b0v = Bb[cl], b1v = Bb[cl + 1];
                float v0 = tanhf(fmaxf(acc[ma][na][0] + b0v, 0.f));
                float v1 = tanhf(fmaxf(acc[ma][na][1] + b1v, 0.f));
                float v2 = tanhf(fmaxf(acc[ma][na][2] + b0v, 0.f));
                float v3 = tanhf(fmaxf(acc[ma][na][3] + b1v, 0.f));
                float2 pA = *reinterpret_cast<const float2*>(prev + (size_t)r0 * 512 + cl);
                float2 pB = *reinterpret_cast<const float2*>(prev + (size_t)r1 * 512 + cl);
                float2 o0 = make_float2(gv0 * v0 + (1.f - gv0) * pA.x,
                                        gv0 * v1 + (1.f - gv0) * pA.y);
                float2 o1 = make_float2(gv1 * v2 + (1.f - gv1) * pB.x,
                                        gv1 * v3 + (1.f - gv1) * pB.y);
                *reinterpret_cast<float2*>(Cb + (size_t)r0 * 512 + cl) = o0;
                *reinterpret_cast<float2*>(Cb + (size_t)r1 * 512 + cl) = o1;
            }
        }
    }
}

// ===========================================================================
// Fused attention core (steps 3+4+5), one CTA per batch b (grid 64), 4-stage:
//   scores[mh][s] = (u[b] @ key_in[:,b,:]^T) * 0.125   (K=512)
//   w = softmax_s(scores); wv[b][mh][d] = w @ value_in[:,b,:]
// ===========================================================================
__global__ __launch_bounds__(256) void fused_attn_kernel(
    const float* __restrict__ u, const float* __restrict__ key_in,
    const float* __restrict__ value_in, float* __restrict__ wvb)
{
    extern __shared__ float smemf[];
    constexpr int NSTG = 4;
    constexpr int PFD = 3, CAP = 2;
    constexpr int A_W  = 2048;            // 64x32 swizzled A
    constexpr int B_W  = 4224;            // max(128x32 swz-NT, 32x132 NN)
    constexpr int STG  = A_W + B_W;       // 6272
    constexpr int WBUF = NSTG * STG;      // softmaxed w, 4 chunks of 64x32
    constexpr int RED  = WBUF + 8192;     // [4][64] reduction buffer

    const int tid = threadIdx.x;
    const int wid = tid >> 5, lane = tid & 31;
    const int g = lane >> 2, tig = lane & 3;
    const int warp_m = wid >> 2, warp_n = wid & 3;
    const int b = blockIdx.x;
    const uint32_t sbase = smem_u32(smemf);

    auto issue1A = [&](int c){
        const int k0 = c << 5;
        const uint32_t sb = sbase + (uint32_t)(c % NSTG) * (STG * 4);
        #pragma unroll
        for (int i = 0; i < 2; i++){
            int f = tid + (i << 8); int r = f >> 3, kq = f & 7;
            cpasync16(sb + (uint32_t)(r * 32 + ((kq ^ (r & 7)) << 2)) * 4,
                      u + (size_t)b * 32768 + (size_t)r * 512 + k0 + (kq << 2));
        }
    };
    auto issue1B = [&](int c){
        const int k0 = c << 5;
        const uint32_t sb = sbase + (uint32_t)(c % NSTG) * (STG * 4);
        #pragma unroll
        for (int i = 0; i < 4; i++){
            int f = tid + (i << 8); int n = f >> 3, kq = f & 7;
            cpasync16(sb + (uint32_t)(A_W + n * 32 + ((kq ^ (n & 7)) << 2)) * 4,
                      key_in + (size_t)n * 32768 + (size_t)b * 512 + k0 + (kq << 2));
        }
    };

    float acc[2][4][4];
    #pragma unroll
    for (int i = 0; i < 2; i++)
        #pragma unroll
        for (int j = 0; j < 4; j++)
            #pragma unroll
            for (int uu = 0; uu < 4; uu++) acc[i][j][uu] = 0.f;

    for (int s = 0; s < PFD; s++) issue1B(s);
    pdl_wait();
    for (int s = 0; s < PFD; s++){ issue1A(s); cp_commit(); }

    for (int c = 0; c < 16; ++c){
        const int rem = 15 - c;
        cp_wait(rem < CAP ? rem : CAP);
        __syncthreads();
        if (c + PFD < 16){
            issue1A(c + PFD);
            issue1B(c + PFD);
            cp_commit();
        }
        const uint32_t* Au = reinterpret_cast<const uint32_t*>(smemf + (c % NSTG) * STG);
        const uint32_t* Bu = Au + A_W;
        #pragma unroll
        for (int ks = 0; ks < 4; ks++){
            const int kk = ks << 3;
            const int cb = kk >> 2;
            uint32_t af[2][4];
            #pragma unroll
            for (int ma = 0; ma < 2; ma++){
                const int r0 = warp_m * 32 + ma * 16 + g;
                const int r1 = r0 + 8;
                af[ma][0] = Au[r0 * 32 + ((cb ^ g) << 2) + tig];
                af[ma][1] = Au[r1 * 32 + ((cb ^ g) << 2) + tig];
                af[ma][2] = Au[r0 * 32 + (((cb + 1) ^ g) << 2) + tig];
                af[ma][3] = Au[r1 * 32 + (((cb + 1) ^ g) << 2) + tig];
            }
            uint32_t bf[4][2];
            #pragma unroll
            for (int na = 0; na < 4; na++){
                const int cl = warp_n * 32 + na * 8 + g;    // cl & 7 == g
                bf[na][0] = Bu[cl * 32 + ((cb ^ g) << 2) + tig];
                bf[na][1] = Bu[cl * 32 + (((cb + 1) ^ g) << 2) + tig];
            }
            #pragma unroll
            for (int ma = 0; ma < 2; ma++)
                #pragma unroll
                for (int na = 0; na < 4; na++)
                    MMA_TF32(acc[ma][na], af[ma], bf[na]);
        }
        __syncthreads();
    }

    // ---------------- softmax over s (rows = mh) ----------------
    #pragma unroll
    for (int ma = 0; ma < 2; ma++)
        #pragma unroll
        for (int na = 0; na < 4; na++)
            #pragma unroll
            for (int uu = 0; uu < 4; uu++) acc[ma][na][uu] *= 0.125f;

    float* red = smemf + RED;
    float rmax[2][2], rsum[2][2];
    #pragma unroll
    for (int ma = 0; ma < 2; ma++)
        #pragma unroll
        for (int hh = 0; hh < 2; hh++){
            float m = -1e30f;
            #pragma unroll
            for (int na = 0; na < 4; na++)
                m = fmaxf(m, fmaxf(acc[ma][na][2*hh], acc[ma][na][2*hh+1]));
            m = fmaxf(m, __shfl_xor_sync(0xffffffffu, m, 1));
            m = fmaxf(m, __shfl_xor_sync(0xffffffffu, m, 2));
            rmax[ma][hh] = m;
        }
    const int rg = warp_m * 32 + g;
    if (tig == 0){
        red[warp_n * 64 + rg]      = rmax[0][0];
        red[warp_n * 64 + rg + 8]  = rmax[0][1];
        red[warp_n * 64 + rg + 16] = rmax[1][0];
        red[warp_n * 64 + rg + 24] = rmax[1][1];
    }
    __syncthreads();
    #pragma unroll
    for (int ma = 0; ma < 2; ma++)
        #pragma unroll
        for (int hh = 0; hh < 2; hh++){
            const int row = rg + ma * 16 + hh * 8;
            rmax[ma][hh] = fmaxf(fmaxf(red[row], red[64 + row]),
                                 fmaxf(red[128 + row], red[192 + row]));
        }
    __syncthreads();
    #pragma unroll
    for (int ma = 0; ma < 2; ma++)
        #pragma unroll
        for (int hh = 0; hh < 2; hh++){
            float s = 0.f;
            #pragma unroll
            for (int na = 0; na < 4; na++){
                float e0 = __expf(acc[ma][na][2*hh]   - rmax[ma][hh]);
                float e1 = __expf(acc[ma][na][2*hh+1] - rmax[ma][hh]);
                acc[ma][na][2*hh] = e0; acc[ma][na][2*hh+1] = e1;
                s += e0 + e1;
            }
            s += __shfl_xor_sync(0xffffffffu, s, 1);
            s += __shfl_xor_sync(0xffffffffu, s, 2);
            rsum[ma][hh] = s;
        }
    if (tig == 0){
        red[warp_n * 64 + rg]      = rsum[0][0];
        red[warp_n * 64 + rg + 8]  = rsum[0][1];
        red[warp_n * 64 + rg + 16] = rsum[1][0];
        red[warp_n * 64 + rg + 24] = rsum[1][1];
    }
    __syncthreads();
    #pragma unroll
    for (int ma = 0; ma < 2; ma++)
        #pragma unroll
        for (int hh = 0; hh < 2; hh++){
            const int row = rg + ma * 16 + hh * 8;
            rsum[ma][hh] = 1.f / (red[row] + red[64 + row] + red[128 + row] + red[192 + row]);
        }

    // write normalized w (tf32) into WBUF in swizzled-A layout (4 chunks of 64x32)
    uint32_t* wb = reinterpret_cast<uint32_t*>(smemf + WBUF);
    #pragma unroll
    for (int ma = 0; ma < 2; ma++)
        #pragma unroll
        for (int hh = 0; hh < 2; hh++){
            const int row = rg + ma * 16 + hh * 8;
            #pragma unroll
            for (int na = 0; na < 4; na++){
                const int c0 = warp_n * 32 + na * 8 + 2 * tig;   // chunk = warp_n
                const int kc = c0 & 31;
                uint2 v = make_uint2(cvt_tf32(acc[ma][na][2*hh]   * rsum[ma][hh]),
                                     cvt_tf32(acc[ma][na][2*hh+1] * rsum[ma][hh]));
                const int word = warp_n * 2048 + row * 32
                               + (((kc >> 2) ^ (row & 7)) << 2) + (kc & 3);
                *reinterpret_cast<uint2*>(wb + word) = v;
            }
        }
    __syncthreads();

    // ---------------- phase 2: wv = w @ value_in[:,b,:] ----------------
    auto issue2 = [&](int cc){
        const int n0 = (cc >> 2) << 7;
        const int k0 = (cc & 3) << 5;
        const uint32_t sb = sbase + (uint32_t)(cc % NSTG) * (STG * 4) + A_W * 4;
        #pragma unroll
        for (int i = 0; i < 4; i++){
            int f = tid + (i << 8); int k = f >> 5, nq = f & 31;
            cpasync16(sb + (uint32_t)(k * 132 + (nq << 2)) * 4,
                      value_in + (size_t)(k0 + k) * 32768 + (size_t)b * 512 + n0 + (nq << 2));
        }
        cp_commit();
    };

    float acc2[2][4][4];
    #pragma unroll
    for (int i = 0; i < 2; i++)
        #pragma unroll
        for (int j = 0; j < 4; j++)
            #pragma unroll
            for (int uu = 0; uu < 4; uu++) acc2[i][j][uu] = 0.f;

    issue2(0); issue2(1); issue2(2);
    for (int cc = 0; cc < 16; ++cc){
        const int rem = 15 - cc;
        cp_wait(rem < CAP ? rem : CAP);
        __syncthreads();
        if (cc + PFD < 16) issue2(cc + PFD);
        const int kc = cc & 3;
        const uint32_t* Au = wb + kc * 2048;
        const uint32_t* Bu = reinterpret_cast<const uint32_t*>(smemf + (cc % NSTG) * STG) + A_W;
        #pragma unroll
        for (int ks = 0; ks < 4; ks++){
            const int kk = ks << 3;
            const int cb = kk >> 2;
            uint32_t af[2][4];
            #pragma unroll
            for (int ma = 0; ma < 2; ma++){
                const int r0 = warp_m * 32 + ma * 16 + g;
                const int r1 = r0 + 8;
                af[ma][0] = Au[r0 * 32 + ((cb ^ g) << 2) + tig];
                af[ma][1] = Au[r1 * 32 + ((cb ^ g) << 2) + tig];
                af[ma][2] = Au[r0 * 32 + (((cb + 1) ^ g) << 2) + tig];
                af[ma][3] = Au[r1 * 32 + (((cb + 1) ^ g) << 2) + tig];
            }
            uint32_t bf[4][2];
            #pragma unroll
            for (int na = 0; na < 4; na++){
                const int cl = warp_n * 32 + na * 8 + g;
                bf[na][0] = Bu[(kk + tig) * 132 + cl];
                bf[na][1] = Bu[(kk + tig + 4) * 132 + cl];
            }
            #pragma unroll
            for (int ma = 0; ma < 2; ma++)
                #pragma unroll
                for (int na = 0; na < 4; na++)
                    MMA_TF32(acc2[ma][na], af[ma], bf[na]);
        }
        __syncthreads();
        if (kc == 3){
            const int n0 = (cc >> 2) << 7;
            #pragma unroll
            for (int ma = 0; ma < 2; ma++){
                const int r0 = warp_m * 32 + ma * 16 + g;
                #pragma unroll
                for (int na = 0; na < 4; na++){
                    const int cl = warp_n * 32 + na * 8 + 2 * tig;
                    *reinterpret_cast<float2*>(wvb + (size_t)b * 32768 + (size_t)r0 * 512 + n0 + cl) =
                        make_float2(acc2[ma][na][0], acc2[ma][na][1]);
                    *reinterpret_cast<float2*>(wvb + (size_t)b * 32768 + (size_t)(r0 + 8) * 512 + n0 + cl) =
                        make_float2(acc2[ma][na][2], acc2[ma][na][3]);
                    acc2[ma][na][0] = acc2[ma][na][1] = acc2[ma][na][2] = acc2[ma][na][3] = 0.f;
                }
            }
        }
    }
}

// ===========================================================================
// LDG+cvt double-buffered tf32 GEMM, NT (B K-contiguous): step 2 only (K=64).
// ===========================================================================
template<int ACT, bool BNT, int BN>
__global__ __launch_bounds__(256) void mma_gemm_kernel(
    const float* __restrict__ A, int lda, int sA1, int sA0,
    const float* __restrict__ W, int ldw, int sW1, int sW0,
    float* __restrict__ C, int ldc, int sC1, int sC0,
    const float* __restrict__ bias, int sB1, int sB0,
    int K, int inner)
{
    extern __shared__ float smemf[];
    constexpr int A_F = 64 * 36;
    constexpr int BSTR = BN + 4;
    constexpr int STAGE_F = A_F + 32 * BSTR;

    const int tid = threadIdx.x;
    const int wid = tid >> 5, lane = tid & 31;
    const int g = lane >> 2, tig = lane & 3;
    const int warp_m = wid >> 2;
    const int warp_n = wid & 3;
    const int batch = blockIdx.y;
    const int b1 = batch / inner;
    const int b0 = batch - b1 * inner;
    const int n0 = blockIdx.x * BN;

    const float* Ab = A + (size_t)b1 * sA1 + (size_t)b0 * sA0;
    const float* Wb = W + (size_t)b1 * sW1 + (size_t)b0 * sW0
                        + (BNT ? (size_t)n0 * ldw : (size_t)n0);
    float*       Cb = C + (size_t)b1 * sC1 + (size_t)b0 * sC0 + n0;
    const float* Bb = bias ? bias + (size_t)b1 * sB1 + (size_t)b0 * sB0 + n0 : nullptr;

    const int NC = K >> 5;
    constexpr int BITER = BN / 32;

    float4 aR[2], bR[BITER];
    auto ldg = [&](int c){
        const int k0 = c << 5;
        #pragma unroll
        for (int i = 0; i < 2; i++){
            int f = tid + (i << 8);
            int r = f >> 3, kq = f & 7;
            aR[i] = *reinterpret_cast<const float4*>(Ab + (size_t)r * lda + k0 + (kq << 2));
        }
        #pragma unroll
        for (int i = 0; i < BITER; i++){
            int f = tid + (i << 8);
            if (BNT){
                int n = f >> 3, kq = f & 7;
                bR[i] = *reinterpret_cast<const float4*>(Wb + (size_t)n * ldw + k0 + (kq << 2));
            } else {
                int k = f / (BN >> 2), nq = f % (BN >> 2);
                bR[i] = *reinterpret_cast<const float4*>(Wb + (size_t)(k0 + k) * ldw + (nq << 2));
            }
        }
    };
    auto sts = [&](int s){
        uint32_t* Au = reinterpret_cast<uint32_t*>(smemf + s * STAGE_F);
        uint32_t* Bu = reinterpret_cast<uint32_t*>(smemf + s * STAGE_F + A_F);
        #pragma unroll
        for (int i = 0; i < 2; i++){
            int f = tid + (i << 8);
            int r = f >> 3, kq = f & 7;
            uint4 v = make_uint4(cvt_tf32(aR[i].x), cvt_tf32(aR[i].y),
                                 cvt_tf32(aR[i].z), cvt_tf32(aR[i].w));
            *reinterpret_cast<uint4*>(&Au[r * 36 + (kq << 2)]) = v;
        }
        #pragma unroll
        for (int i = 0; i < BITER; i++){
            int f = tid + (i << 8);
            if (BNT){
                int n = f >> 3, kq = f & 7;
                Bu[(4 * kq + 0) * BSTR + n] = cvt_tf32(bR[i].x);
                Bu[(4 * kq + 1) * BSTR + n] = cvt_tf32(bR[i].y);
                Bu[(4 * kq + 2) * BSTR + n] = cvt_tf32(bR[i].z);
                Bu[(4 * kq + 3) * BSTR + n] = cvt_tf32(bR[i].w);
            } else {
                int k = f / (BN >> 2), nq = f % (BN >> 2);
                uint4 v = make_uint4(cvt_tf32(bR[i].x), cvt_tf32(bR[i].y),
                                     cvt_tf32(bR[i].z), cvt_tf32(bR[i].w));
                *reinterpret_cast<uint4*>(&Bu[k * BSTR + (nq << 2)]) = v;
            }
        }
    };

    constexpr int NA = BN / 32;
    float acc[2][NA][4];
    #pragma unroll
    for (int i = 0; i < 2; i++)
        #pragma unroll
        for (int j = 0; j < NA; j++)
            #pragma unroll
            for (int u = 0; u < 4; u++) acc[i][j][u] = 0.f;

    pdl_wait();
    ldg(0);
    sts(0);
    if (NC > 1) ldg(1);
    __syncthreads();

    for (int c = 0; c < NC; ++c){
        const int s = c & 1;
        if (c + 1 < NC){
            sts(s ^ 1);
            if (c + 2 < NC) ldg(c + 2);
        }
        const uint32_t* Au = reinterpret_cast<const uint32_t*>(smemf + s * STAGE_F);
        const uint32_t* Bu = reinterpret_cast<const uint32_t*>(smemf + s * STAGE_F + A_F);
        #pragma unroll
        for (int ks = 0; ks < 4; ks++){
            const int kk = ks << 3;
            uint32_t af[2][4];
            #pragma unroll
            for (int ma = 0; ma < 2; ma++){
                const int r0 = warp_m * 32 + ma * 16 + g;
                af[ma][0] = Au[r0 * 36 + kk + tig];
                af[ma][1] = Au[(r0 + 8) * 36 + kk + tig];
                af[ma][2] = Au[r0 * 36 + kk + tig + 4];
                af[ma][3] = Au[(r0 + 8) * 36 + kk + tig + 4];
            }
            uint32_t bf[NA][2];
            #pragma unroll
            for (int na = 0; na < NA; na++){
                const int cl = warp_n * (BN / 4) + na * 8 + g;
                bf[na][0] = Bu[(kk + tig) * BSTR + cl];
                bf[na][1] = Bu[(kk + tig + 4) * BSTR + cl];
            }
            #pragma unroll
            for (int ma = 0; ma < 2; ma++)
                #pragma unroll
                for (int na = 0; na < NA; na++)
                    MMA_TF32(acc[ma][na], af[ma], bf[na]);
        }
        __syncthreads();
    }

    #pragma unroll
    for (int ma = 0; ma < 2; ma++){
        const int r0 = warp_m * 32 + ma * 16 + g;
        #pragma unroll
        for (int na = 0; na < NA; na++){
            const int cl = warp_n * (BN / 4) + na * 8 + 2 * tig;
            float b0v = Bb ? Bb[cl] : 0.f;
            float b1v = Bb ? Bb[cl + 1] : 0.f;
            float v0 = acc[ma][na][0] + b0v, v1 = acc[ma][na][1] + b1v;
            float v2 = acc[ma][na][2] + b0v, v3 = acc[ma][na][3] + b1v;
            if (ACT >= 1){
                v0 = fmaxf(v0, 0.f); v1 = fmaxf(v1, 0.f);
                v2 = fmaxf(v2, 0.f); v3 = fmaxf(v3, 0.f);
            }
            *reinterpret_cast<float2*>(Cb + (size_t)r0 * ldc + cl) = make_float2(v0, v1);
            *reinterpret_cast<float2*>(Cb + (size_t)(r0 + 8) * ldc + cl) = make_float2(v2, v3);
        }
    }
}

// Host-side PDL launcher.
template<typename F, typename... Args>
static inline void launch_pdl(F f, dim3 grid, dim3 block, size_t smem, Args... args)
{
    cudaLaunchConfig_t cfg = {};
    cfg.gridDim = grid;
    cfg.blockDim = block;
    cfg.dynamicSmemBytes = smem;
    cudaLaunchAttribute attr[1];
    attr[0].id = cudaLaunchAttributeProgrammaticStreamSerialization;
    attr[0].val.programmaticStreamSerializationAllowed = 1;
    cfg.attrs = attr;
    cfg.numAttrs = 1;
    cudaLaunchKernelEx(&cfg, f, args...);
}

extern "C" void kernel_launch(void* const* d_in, const int* in_sizes, int n_in,
                              void* d_out, int out_size)
{
    (void)in_sizes; (void)n_in; (void)out_size;
    const float* prev_state = (const float*)d_in[0];
    const float* prev_query = (const float*)d_in[1];
    const float* prev_key   = (const float*)d_in[2];
    const float* prev_value = (const float*)d_in[3];
    const float* key_in     = (const float*)d_in[4];
    const float* value_in   = (const float*)d_in[5];
    const float* Wq = (const float*)d_in[6];
    const float* bq = (const float*)d_in[7];
    const float* Wk = (const float*)d_in[8];
    // d_in[9] = bk: softmax invariant to per-(m,b,h) shift over s -> unused.
    const float* Wv = (const float*)d_in[10];
    const float* bv = (const float*)d_in[11];
    const float* Wo = (const float*)d_in[12];
    const float* bo = (const float*)d_in[13];
    const float* W1  = (const float*)d_in[14];
    const float* b1  = (const float*)d_in[15];
    const float* W2  = (const float*)d_in[16];
    const float* b2  = (const float*)d_in[17];
    const float* Wg1 = (const float*)d_in[18];
    const float* bg1 = (const float*)d_in[19];
    const float* Wg2 = (const float*)d_in[20];
    const float* bg2 = (const float*)d_in[21];
    float* out = (float*)d_out;

    float* scratch = nullptr;
    cudaGetSymbolAddress((void**)&scratch, g_scratch);
    float* q     = scratch;
    float* u     = scratch + 262144;
    float* wvb   = scratch + 2883584;
    float* ao    = scratch + 4980736;
    float* x     = scratch + 5242880;
    float* h     = scratch + 5767168;
    float* gatez = scratch + 7864320;   // [8][32][64]

    const float* NOB = nullptr;
    EpiArgs E0{};

    // smem: NSTG * (A 2048 + B 32*(BN+4)) + 256 guard, floats
    const int ASM128 = (4 * (2048 + 4224) + 256) * 4;   // 101376
    const int ASM64  = (5 * (2048 + 2176) + 256) * 4;   // 85504
    const int NTSM128 = 2 * (64 * 36 + 32 * 132) * 4;   // 52224
    const int FSM = (4 * 6272 + 8192 + 256) * 4;        // 134144
    cudaFuncSetAttribute(mma_async_kernel<0,128,0,4>, cudaFuncAttributeMaxDynamicSharedMemorySize, ASM128);
    cudaFuncSetAttribute(mma_async_kernel<0, 64,0,5>, cudaFuncAttributeMaxDynamicSharedMemorySize, ASM64);
    cudaFuncSetAttribute(mma_async_kernel<1,128,4,4>, cudaFuncAttributeMaxDynamicSharedMemorySize, ASM128);
    cudaFuncSetAttribute(mma_async_kernel<1,128,3,4>, cudaFuncAttributeMaxDynamicSharedMemorySize, ASM128);
    cudaFuncSetAttribute(mma_async_kernel<2,128,2,4>, cudaFuncAttributeMaxDynamicSharedMemorySize, ASM128);
    cudaFuncSetAttribute(mma_gemm_kernel<0,true,128>, cudaFuncAttributeMaxDynamicSharedMemorySize, NTSM128);
    cudaFuncSetAttribute(fused_attn_kernel, cudaFuncAttributeMaxDynamicSharedMemorySize, FSM);

    // 1) q = prev_query @ Wq + bq
    launch_pdl(mma_async_kernel<0,128,0,4>, dim3(4,8), dim3(256), ASM128,
        prev_query,512,32768,0,  Wq,512,262144,0,  q,512,32768,0,  bq,512,0,  512,1, E0);

    // 2) u[b][mh][d] = sum_j q[m][b][h64+j] * Wk[m][d][h64+j]
    launch_pdl(mma_gemm_kernel<0,true,128>, dim3(4,64), dim3(256), NTSM128,
        q,512,32768,64,  Wk,512,262144,64,  u,32768,4096,512,  NOB,0,0,  64,8);

    // 3-5) fused scores -> softmax -> wv  (per batch b)
    launch_pdl(fused_attn_kernel, dim3(64), dim3(256), FSM, u, key_in, value_in, wvb);

    // 6) ao = wv @ Wv-slices + bv   (5-stage pipeline: worst latency-bound kernel)
    launch_pdl(mma_async_kernel<0,64,0,5>, dim3(1,64), dim3(256), ASM64,
        wvb,32768,4096,512,  Wv,512,262144,64,  ao,512,32768,64,  bv,512,64,  512,8, E0);

    // 7) x[:, :D] = relu(ao @ Wo + bo); x[:, D:] = relu(prev_state)  (EPI4)
    {
        EpiArgs E4{};
        E4.p3 = prev_state;
        launch_pdl(mma_async_kernel<1,128,4,4>, dim3(4,8), dim3(256), ASM128,
            ao,512,32768,0,  Wo,512,262144,0,  x,1024,65536,0,  bo,512,0,  512,1, E4);
    }

    // 8) dual MLP: bx<8 -> h = relu(x@W1+b1); bx>=8 -> gate partials via Wg1/bg1/Wg2
    {
        EpiArgs E3{};
        E3.wg2 = Wg2; E3.gatez = gatez; E3.wAlt = Wg1; E3.bAlt = bg1;
        launch_pdl(mma_async_kernel<1,128,3,4>, dim3(16,32), dim3(256), ASM128,
            x,1024,0,65536,  W1,1024,8388608,1048576,  h,1024,524288,65536,  b1,8192,1024,  1024,8, E3);
    }

    // 9) final: v=tanh(relu(h@W2+b2)); gv=sigmoid(sum gatez + bg2); mix with prev
    {
        EpiArgs E2{};
        E2.gzin = gatez; E2.bg2 = bg2;
        E2.p0 = prev_query; E2.p1 = prev_key; E2.p2 = prev_value; E2.p3 = prev_state;
        launch_pdl(mma_async_kernel<2,128,2,4>, dim3(4,32), dim3(256), ASM128,
            h,1024,524288,65536,  W2,512,4194304,524288,  out,512,0,0,  b2,4096,512,  1024,8, E2);
    }
}